// round 1
// baseline (speedup 1.0000x reference)
#include <cuda_runtime.h>
#include <cuda_bf16.h>

#define N_NODES 100000
#define N_EDGES 1600000
#define DF      64

// Scratch (no runtime allocation allowed)
__device__ float g_norm[N_NODES];          // deg -> rsqrt(max(deg,1))
__device__ float g_S1[N_NODES * DF];       // S1[d] = sum_e norm[s]*feat[s]
__device__ float g_S2[N_NODES * DF];       // S2[d] = sum_e -norm[s]^2*S1[s]

// ---------------------------------------------------------------------------
// 1) degree count: one RED per edge
// ---------------------------------------------------------------------------
__global__ void deg_kernel(const int* __restrict__ dst) {
    int t = blockIdx.x * blockDim.x + threadIdx.x;
    if (t < N_EDGES) atomicAdd(&g_norm[dst[t]], 1.0f);   // result unused -> REDG
}

// 2) norm = rsqrt(max(deg,1)) in place
__global__ void norm_kernel() {
    int t = blockIdx.x * blockDim.x + threadIdx.x;
    if (t < N_NODES) {
        float d = g_norm[t];
        g_norm[t] = rsqrtf(fmaxf(d, 1.0f));
    }
}

// ---------------------------------------------------------------------------
// 3) edge scatter: 16 threads per edge, float4 vector RED into destination row
//    PASS2=false: out += norm[s] * feat[s]
//    PASS2=true : out += (-norm[s]^2) * S1[s]     (folds Tx1 = -norm*S1)
// ---------------------------------------------------------------------------
__device__ __forceinline__ void red_add_v4(float* p, float4 v) {
    asm volatile("red.global.add.v4.f32 [%0], {%1,%2,%3,%4};"
                 :: "l"(p), "f"(v.x), "f"(v.y), "f"(v.z), "f"(v.w)
                 : "memory");
}

template <bool PASS2>
__global__ void scatter_kernel(const float4* __restrict__ x,
                               const int*    __restrict__ src,
                               const int*    __restrict__ dst,
                               float*        __restrict__ out) {
    int t = blockIdx.x * blockDim.x + threadIdx.x;     // N_EDGES*16 = 25.6M
    if (t >= N_EDGES * (DF / 4)) return;
    int e = t >> 4;
    int c = t & 15;
    int s = __ldg(&src[e]);
    int d = __ldg(&dst[e]);
    float ns   = __ldg(&g_norm[s]);
    float coef = PASS2 ? (-ns * ns) : ns;
    float4 v = x[s * 16 + c];
    v.x *= coef; v.y *= coef; v.z *= coef; v.w *= coef;
    red_add_v4(out + (d * 64 + c * 4), v);
}

// ---------------------------------------------------------------------------
// 4) fused GEMM: out = feat@W0 + (-norm*S1)@W1 + (-2*norm*S2 - feat)@W2 + bias
//    M=100000, K=3*64, N=64. 64-row tile / block, 256 threads, 4x4 micro-tile.
// ---------------------------------------------------------------------------
__global__ __launch_bounds__(256)
void gemm_kernel(const float* __restrict__ feat,
                 const float* __restrict__ W,     // [3][64][64]
                 const float* __restrict__ bias,  // [64]
                 float*       __restrict__ out) {
    __shared__ float As[64][65];   // [k][m], pad->conflict-free transposed store
    __shared__ float Ws[64][64];   // [k][n]

    const int m0 = blockIdx.x * 64;
    const int tx = threadIdx.x & 15;   // n-group: cols tx*4 .. tx*4+3
    const int ty = threadIdx.x >> 4;   // m-group: rows ty*4 .. ty*4+3

    float acc[4][4];
#pragma unroll
    for (int i = 0; i < 4; ++i)
#pragma unroll
        for (int j = 0; j < 4; ++j) acc[i][j] = 0.0f;

    for (int p = 0; p < 3; ++p) {
        // --- stage W[p] (coalesced, conflict-free) ---
#pragma unroll
        for (int i = 0; i < 16; ++i) {
            int idx = threadIdx.x + i * 256;               // 0..4095
            Ws[idx >> 6][idx & 63] = W[p * 4096 + idx];
        }
        // --- stage A tile (compute Tx1/Tx2 on the fly) ---
#pragma unroll
        for (int i = 0; i < 16; ++i) {
            int idx  = threadIdx.x + i * 256;
            int m    = idx >> 6;
            int k    = idx & 63;
            int node = m0 + m;
            float v  = 0.0f;
            if (node < N_NODES) {
                int g = node * 64 + k;
                if (p == 0)      v = feat[g];
                else if (p == 1) v = -g_norm[node] * g_S1[g];
                else             v = fmaf(-2.0f * g_norm[node], g_S2[g], -feat[g]);
            }
            As[k][m] = v;
        }
        __syncthreads();

        // --- inner product ---
#pragma unroll
        for (int k = 0; k < 64; ++k) {
            float a0 = As[k][ty * 4 + 0];
            float a1 = As[k][ty * 4 + 1];
            float a2 = As[k][ty * 4 + 2];
            float a3 = As[k][ty * 4 + 3];
            float4 w = *(const float4*)&Ws[k][tx * 4];
            acc[0][0] = fmaf(a0, w.x, acc[0][0]); acc[0][1] = fmaf(a0, w.y, acc[0][1]);
            acc[0][2] = fmaf(a0, w.z, acc[0][2]); acc[0][3] = fmaf(a0, w.w, acc[0][3]);
            acc[1][0] = fmaf(a1, w.x, acc[1][0]); acc[1][1] = fmaf(a1, w.y, acc[1][1]);
            acc[1][2] = fmaf(a1, w.z, acc[1][2]); acc[1][3] = fmaf(a1, w.w, acc[1][3]);
            acc[2][0] = fmaf(a2, w.x, acc[2][0]); acc[2][1] = fmaf(a2, w.y, acc[2][1]);
            acc[2][2] = fmaf(a2, w.z, acc[2][2]); acc[2][3] = fmaf(a2, w.w, acc[2][3]);
            acc[3][0] = fmaf(a3, w.x, acc[3][0]); acc[3][1] = fmaf(a3, w.y, acc[3][1]);
            acc[3][2] = fmaf(a3, w.z, acc[3][2]); acc[3][3] = fmaf(a3, w.w, acc[3][3]);
        }
        __syncthreads();
    }

    // --- epilogue: + bias, float4 stores ---
    float4 b4 = *(const float4*)&bias[tx * 4];
#pragma unroll
    for (int i = 0; i < 4; ++i) {
        int node = m0 + ty * 4 + i;
        if (node < N_NODES) {
            float4 o;
            o.x = acc[i][0] + b4.x;
            o.y = acc[i][1] + b4.y;
            o.z = acc[i][2] + b4.z;
            o.w = acc[i][3] + b4.w;
            *(float4*)&out[node * 64 + tx * 4] = o;
        }
    }
}

// ---------------------------------------------------------------------------
extern "C" void kernel_launch(void* const* d_in, const int* in_sizes, int n_in,
                              void* d_out, int out_size) {
    const float* feat = (const float*)d_in[0];
    const float* W    = (const float*)d_in[1];
    const float* bias = (const float*)d_in[2];
    const int*   esrc = (const int*)d_in[3];
    const int*   edst = (const int*)d_in[4];
    float*       out  = (float*)d_out;

    void *p_norm, *p_s1, *p_s2;
    cudaGetSymbolAddress(&p_norm, g_norm);
    cudaGetSymbolAddress(&p_s1,   g_S1);
    cudaGetSymbolAddress(&p_s2,   g_S2);

    cudaMemsetAsync(p_norm, 0, N_NODES * sizeof(float));
    cudaMemsetAsync(p_s1,   0, (size_t)N_NODES * DF * sizeof(float));
    cudaMemsetAsync(p_s2,   0, (size_t)N_NODES * DF * sizeof(float));

    deg_kernel<<<(N_EDGES + 255) / 256, 256>>>(edst);
    norm_kernel<<<(N_NODES + 255) / 256, 256>>>();

    const int scat_items  = N_EDGES * (DF / 4);
    const int scat_blocks = (scat_items + 255) / 256;
    scatter_kernel<false><<<scat_blocks, 256>>>((const float4*)feat, esrc, edst,
                                                (float*)p_s1);
    scatter_kernel<true><<<scat_blocks, 256>>>((const float4*)p_s1, esrc, edst,
                                               (float*)p_s2);

    gemm_kernel<<<(N_NODES + 63) / 64, 256>>>(feat, W, bias, out);
}

// round 2
// speedup vs baseline: 1.3230x; 1.3230x over previous
#include <cuda_runtime.h>
#include <cuda_bf16.h>

#define N_NODES 100000
#define N_EDGES 1600000
#define DF      64
#define NB      ((N_NODES + 1023) / 1024)   // 98 scan blocks

// ---- scratch (static device memory; no runtime allocation) ----
__device__ int   g_degi[N_NODES];
__device__ int   g_off [N_NODES + 1];
__device__ int   g_cur [N_NODES];
__device__ int   g_bsum[NB];
__device__ int   g_boff[NB];
__device__ int   g_srt [N_EDGES];          // src node per CSR slot (grouped by dst)
__device__ float g_norm[N_NODES];
__device__ float g_A [N_NODES * DF];       // y = norm*feat, later z = -norm^2*S1
__device__ float g_S1[N_NODES * DF];
__device__ float g_S2[N_NODES * DF];

// ---------------------------------------------------------------------------
// degree histogram
__global__ void deg_kernel(const int* __restrict__ dst) {
    int t = blockIdx.x * blockDim.x + threadIdx.x;
    if (t < N_EDGES) atomicAdd(&g_degi[dst[t]], 1);
}

// scan level 1: per-block exclusive scan of 1024 degrees + block totals
__global__ __launch_bounds__(1024) void scan1_kernel() {
    __shared__ int sh[1024];
    int i = blockIdx.x * 1024 + threadIdx.x;
    int v = (i < N_NODES) ? g_degi[i] : 0;
    sh[threadIdx.x] = v;
    __syncthreads();
#pragma unroll
    for (int d = 1; d < 1024; d <<= 1) {
        int t = (threadIdx.x >= d) ? sh[threadIdx.x - d] : 0;
        __syncthreads();
        sh[threadIdx.x] += t;
        __syncthreads();
    }
    if (i < N_NODES) g_off[i] = sh[threadIdx.x] - v;   // exclusive within block
    if (threadIdx.x == 1023) g_bsum[blockIdx.x] = sh[1023];
}

// scan level 2: exclusive scan of the 98 block sums (single block)
__global__ void scan2_kernel() {
    __shared__ int sh[128];
    int t = threadIdx.x;
    int v = (t < NB) ? g_bsum[t] : 0;
    sh[t] = v;
    __syncthreads();
#pragma unroll
    for (int d = 1; d < 128; d <<= 1) {
        int u = (t >= d) ? sh[t - d] : 0;
        __syncthreads();
        sh[t] += u;
        __syncthreads();
    }
    if (t < NB) g_boff[t] = sh[t] - v;
}

// scan level 3: finalize offsets, cursors, norm
__global__ void scan3_kernel() {
    int i = blockIdx.x * blockDim.x + threadIdx.x;
    if (i < N_NODES) {
        int off = g_off[i] + g_boff[i >> 10];
        g_off[i] = off;
        g_cur[i] = off;
        g_norm[i] = rsqrtf(fmaxf((float)g_degi[i], 1.0f));
    }
    if (i == 0) g_off[N_NODES] = N_EDGES;
}

// CSR fill: slot per incoming edge
__global__ void fill_kernel(const int* __restrict__ src, const int* __restrict__ dst) {
    int e = blockIdx.x * blockDim.x + threadIdx.x;
    if (e < N_EDGES) {
        int pos = atomicAdd(&g_cur[dst[e]], 1);
        g_srt[pos] = src[e];
    }
}

// ---------------------------------------------------------------------------
// elementwise pre-scales
__global__ void prescale1_kernel(const float4* __restrict__ feat) {  // A = norm*feat
    int t = blockIdx.x * blockDim.x + threadIdx.x;
    if (t >= N_NODES * (DF / 4)) return;
    float n = g_norm[t >> 4];
    float4 v = feat[t];
    v.x *= n; v.y *= n; v.z *= n; v.w *= n;
    ((float4*)g_A)[t] = v;
}
__global__ void prescale2_kernel() {                                 // A = -norm^2*S1
    int t = blockIdx.x * blockDim.x + threadIdx.x;
    if (t >= N_NODES * (DF / 4)) return;
    float n = g_norm[t >> 4];
    float c = -n * n;
    float4 v = ((const float4*)g_S1)[t];
    v.x *= c; v.y *= c; v.z *= c; v.w *= c;
    ((float4*)g_A)[t] = v;
}

// ---------------------------------------------------------------------------
// gather: 16 lanes per dst node, register accumulate, single write
__global__ __launch_bounds__(256)
void gather_kernel(const float4* __restrict__ x, float4* __restrict__ out) {
    int node = blockIdx.x * 16 + (threadIdx.x >> 4);
    int c    = threadIdx.x & 15;
    if (node >= N_NODES) return;
    int j   = g_off[node];
    int end = g_off[node + 1];
    float4 acc = make_float4(0.f, 0.f, 0.f, 0.f);

    for (; j + 3 < end; j += 4) {
        int s0 = g_srt[j], s1 = g_srt[j + 1], s2 = g_srt[j + 2], s3 = g_srt[j + 3];
        float4 v0 = x[s0 * 16 + c];
        float4 v1 = x[s1 * 16 + c];
        float4 v2 = x[s2 * 16 + c];
        float4 v3 = x[s3 * 16 + c];
        acc.x += (v0.x + v1.x) + (v2.x + v3.x);
        acc.y += (v0.y + v1.y) + (v2.y + v3.y);
        acc.z += (v0.z + v1.z) + (v2.z + v3.z);
        acc.w += (v0.w + v1.w) + (v2.w + v3.w);
    }
    for (; j < end; ++j) {
        int s = g_srt[j];
        float4 v = x[s * 16 + c];
        acc.x += v.x; acc.y += v.y; acc.z += v.z; acc.w += v.w;
    }
    out[node * 16 + c] = acc;
}

// ---------------------------------------------------------------------------
// fused GEMM: out = feat@W0 + (-norm*S1)@W1 + (-2*norm*S2 - feat)@W2 + bias
__global__ __launch_bounds__(256)
void gemm_kernel(const float* __restrict__ feat,
                 const float* __restrict__ W,
                 const float* __restrict__ bias,
                 float*       __restrict__ out) {
    __shared__ float As[64][65];
    __shared__ float Ws[64][64];

    const int m0 = blockIdx.x * 64;
    const int tx = threadIdx.x & 15;
    const int ty = threadIdx.x >> 4;

    float acc[4][4];
#pragma unroll
    for (int i = 0; i < 4; ++i)
#pragma unroll
        for (int j = 0; j < 4; ++j) acc[i][j] = 0.0f;

    for (int p = 0; p < 3; ++p) {
#pragma unroll
        for (int i = 0; i < 16; ++i) {
            int idx = threadIdx.x + i * 256;
            Ws[idx >> 6][idx & 63] = W[p * 4096 + idx];
        }
#pragma unroll
        for (int i = 0; i < 16; ++i) {
            int idx  = threadIdx.x + i * 256;
            int m    = idx >> 6;
            int k    = idx & 63;
            int node = m0 + m;
            float v  = 0.0f;
            if (node < N_NODES) {
                int g = node * 64 + k;
                if (p == 0)      v = feat[g];
                else if (p == 1) v = -g_norm[node] * g_S1[g];
                else             v = fmaf(-2.0f * g_norm[node], g_S2[g], -feat[g]);
            }
            As[k][m] = v;
        }
        __syncthreads();

#pragma unroll
        for (int k = 0; k < 64; ++k) {
            float a0 = As[k][ty * 4 + 0];
            float a1 = As[k][ty * 4 + 1];
            float a2 = As[k][ty * 4 + 2];
            float a3 = As[k][ty * 4 + 3];
            float4 w = *(const float4*)&Ws[k][tx * 4];
            acc[0][0] = fmaf(a0, w.x, acc[0][0]); acc[0][1] = fmaf(a0, w.y, acc[0][1]);
            acc[0][2] = fmaf(a0, w.z, acc[0][2]); acc[0][3] = fmaf(a0, w.w, acc[0][3]);
            acc[1][0] = fmaf(a1, w.x, acc[1][0]); acc[1][1] = fmaf(a1, w.y, acc[1][1]);
            acc[1][2] = fmaf(a1, w.z, acc[1][2]); acc[1][3] = fmaf(a1, w.w, acc[1][3]);
            acc[2][0] = fmaf(a2, w.x, acc[2][0]); acc[2][1] = fmaf(a2, w.y, acc[2][1]);
            acc[2][2] = fmaf(a2, w.z, acc[2][2]); acc[2][3] = fmaf(a2, w.w, acc[2][3]);
            acc[3][0] = fmaf(a3, w.x, acc[3][0]); acc[3][1] = fmaf(a3, w.y, acc[3][1]);
            acc[3][2] = fmaf(a3, w.z, acc[3][2]); acc[3][3] = fmaf(a3, w.w, acc[3][3]);
        }
        __syncthreads();
    }

    float4 b4 = *(const float4*)&bias[tx * 4];
#pragma unroll
    for (int i = 0; i < 4; ++i) {
        int node = m0 + ty * 4 + i;
        if (node < N_NODES) {
            float4 o;
            o.x = acc[i][0] + b4.x;
            o.y = acc[i][1] + b4.y;
            o.z = acc[i][2] + b4.z;
            o.w = acc[i][3] + b4.w;
            *(float4*)&out[node * 64 + tx * 4] = o;
        }
    }
}

// ---------------------------------------------------------------------------
extern "C" void kernel_launch(void* const* d_in, const int* in_sizes, int n_in,
                              void* d_out, int out_size) {
    const float* feat = (const float*)d_in[0];
    const float* W    = (const float*)d_in[1];
    const float* bias = (const float*)d_in[2];
    const int*   esrc = (const int*)d_in[3];
    const int*   edst = (const int*)d_in[4];
    float*       out  = (float*)d_out;

    void* p_degi;  cudaGetSymbolAddress(&p_degi, g_degi);
    void* p_A;     cudaGetSymbolAddress(&p_A,    g_A);
    void* p_S1;    cudaGetSymbolAddress(&p_S1,   g_S1);
    void* p_S2;    cudaGetSymbolAddress(&p_S2,   g_S2);

    cudaMemsetAsync(p_degi, 0, N_NODES * sizeof(int));

    deg_kernel <<<(N_EDGES + 255) / 256, 256>>>(edst);
    scan1_kernel<<<NB, 1024>>>();
    scan2_kernel<<<1, 128>>>();
    scan3_kernel<<<(N_NODES + 255) / 256, 256>>>();
    fill_kernel <<<(N_EDGES + 255) / 256, 256>>>(esrc, edst);

    const int ew = N_NODES * (DF / 4);
    prescale1_kernel<<<(ew + 255) / 256, 256>>>((const float4*)feat);
    gather_kernel   <<<(N_NODES + 15) / 16, 256>>>((const float4*)p_A, (float4*)p_S1);
    prescale2_kernel<<<(ew + 255) / 256, 256>>>();
    gather_kernel   <<<(N_NODES + 15) / 16, 256>>>((const float4*)p_A, (float4*)p_S2);

    gemm_kernel<<<(N_NODES + 63) / 64, 256>>>(feat, W, bias, out);
}

// round 4
// speedup vs baseline: 1.6861x; 1.2745x over previous
#include <cuda_runtime.h>
#include <cuda_bf16.h>

#define N_NODES 100000
#define N_EDGES 1600000
#define DF      64
#define NB      ((N_NODES + 1023) / 1024)   // 98 scan blocks

// ---- scratch (static device memory; no runtime allocation) ----
__device__ int   g_degi[N_NODES];
__device__ int   g_off [N_NODES + 1];
__device__ int   g_cur [N_NODES];
__device__ int   g_bsum[NB];
__device__ int   g_boff[NB];
__device__ int   g_srt [N_EDGES];          // src node per CSR slot (grouped by dst)
__device__ float g_norm [N_NODES];         // rsqrt(max(deg,1))
__device__ float g_rnorm[N_NODES];         // sqrt(max(deg,1)) = 1/norm
__device__ float g_A [N_NODES * DF];       // norm*feat          (gather1 input)
__device__ float g_B [N_NODES * DF];       // -norm^2*S1         (gather2 input; Tx1 = B*rnorm)
__device__ float g_T2[N_NODES * DF];       // Tx2 = -2*norm*S2 - feat

// ---------------------------------------------------------------------------
__global__ void deg_kernel(const int* __restrict__ dst) {
    int t = blockIdx.x * blockDim.x + threadIdx.x;
    if (t < N_EDGES) atomicAdd(&g_degi[dst[t]], 1);
}

__global__ __launch_bounds__(1024) void scan1_kernel() {
    __shared__ int sh[1024];
    int i = blockIdx.x * 1024 + threadIdx.x;
    int v = (i < N_NODES) ? g_degi[i] : 0;
    sh[threadIdx.x] = v;
    __syncthreads();
#pragma unroll
    for (int d = 1; d < 1024; d <<= 1) {
        int t = (threadIdx.x >= d) ? sh[threadIdx.x - d] : 0;
        __syncthreads();
        sh[threadIdx.x] += t;
        __syncthreads();
    }
    if (i < N_NODES) g_off[i] = sh[threadIdx.x] - v;
    if (threadIdx.x == 1023) g_bsum[blockIdx.x] = sh[1023];
}

__global__ void scan2_kernel() {
    __shared__ int sh[128];
    int t = threadIdx.x;
    int v = (t < NB) ? g_bsum[t] : 0;
    sh[t] = v;
    __syncthreads();
#pragma unroll
    for (int d = 1; d < 128; d <<= 1) {
        int u = (t >= d) ? sh[t - d] : 0;
        __syncthreads();
        sh[t] += u;
        __syncthreads();
    }
    if (t < NB) g_boff[t] = sh[t] - v;
}

__global__ void scan3_kernel() {
    int i = blockIdx.x * blockDim.x + threadIdx.x;
    if (i < N_NODES) {
        int off = g_off[i] + g_boff[i >> 10];
        g_off[i] = off;
        g_cur[i] = off;
        float d = fmaxf((float)g_degi[i], 1.0f);
        g_norm[i]  = rsqrtf(d);
        g_rnorm[i] = sqrtf(d);
    }
    if (i == 0) g_off[N_NODES] = N_EDGES;
}

__global__ void fill_kernel(const int* __restrict__ src, const int* __restrict__ dst) {
    int e = blockIdx.x * blockDim.x + threadIdx.x;
    if (e < N_EDGES) {
        int pos = atomicAdd(&g_cur[dst[e]], 1);
        g_srt[pos] = src[e];
    }
}

// ---------------------------------------------------------------------------
__global__ void prescale1_kernel(const float4* __restrict__ feat) {  // A = norm*feat
    int t = blockIdx.x * blockDim.x + threadIdx.x;
    if (t >= N_NODES * (DF / 4)) return;
    float n = g_norm[t >> 4];
    float4 v = feat[t];
    v.x *= n; v.y *= n; v.z *= n; v.w *= n;
    ((float4*)g_A)[t] = v;
}

// ---------------------------------------------------------------------------
// gather core: 16 lanes per dst node, register accumulate, unroll 8
__device__ __forceinline__ float4 gather_row(const float4* __restrict__ x,
                                             int node, int c) {
    int j   = g_off[node];
    int end = g_off[node + 1];
    float4 acc = make_float4(0.f, 0.f, 0.f, 0.f);
    for (; j + 8 <= end; j += 8) {
        int s[8];
#pragma unroll
        for (int u = 0; u < 8; ++u) s[u] = __ldg(&g_srt[j + u]);
        float4 v[8];
#pragma unroll
        for (int u = 0; u < 8; ++u) v[u] = x[s[u] * 16 + c];
#pragma unroll
        for (int u = 0; u < 8; ++u) {
            acc.x += v[u].x; acc.y += v[u].y; acc.z += v[u].z; acc.w += v[u].w;
        }
    }
    for (; j + 4 <= end; j += 4) {
        int s0 = g_srt[j], s1 = g_srt[j + 1], s2 = g_srt[j + 2], s3 = g_srt[j + 3];
        float4 v0 = x[s0 * 16 + c], v1 = x[s1 * 16 + c];
        float4 v2 = x[s2 * 16 + c], v3 = x[s3 * 16 + c];
        acc.x += (v0.x + v1.x) + (v2.x + v3.x);
        acc.y += (v0.y + v1.y) + (v2.y + v3.y);
        acc.z += (v0.z + v1.z) + (v2.z + v3.z);
        acc.w += (v0.w + v1.w) + (v2.w + v3.w);
    }
    for (; j < end; ++j) {
        float4 v = x[g_srt[j] * 16 + c];
        acc.x += v.x; acc.y += v.y; acc.z += v.z; acc.w += v.w;
    }
    return acc;
}

// gather1: B = -norm^2 * S1   (S1 = sum of A rows)
__global__ __launch_bounds__(256)
void gather1_kernel(const float4* __restrict__ x, float4* __restrict__ B) {
    int node = blockIdx.x * 16 + (threadIdx.x >> 4);
    int c    = threadIdx.x & 15;
    if (node >= N_NODES) return;
    float4 acc = gather_row(x, node, c);
    float n = g_norm[node];
    float cf = -n * n;
    acc.x *= cf; acc.y *= cf; acc.z *= cf; acc.w *= cf;
    B[node * 16 + c] = acc;
}

// gather2: Tx2 = -2*norm*S2 - feat   (S2 = sum of B rows)
__global__ __launch_bounds__(256)
void gather2_kernel(const float4* __restrict__ x,
                    const float4* __restrict__ feat,
                    float4*       __restrict__ T2) {
    int node = blockIdx.x * 16 + (threadIdx.x >> 4);
    int c    = threadIdx.x & 15;
    if (node >= N_NODES) return;
    float4 acc = gather_row(x, node, c);
    float cf = -2.0f * g_norm[node];
    float4 f = feat[node * 16 + c];
    float4 o;
    o.x = fmaf(cf, acc.x, -f.x);
    o.y = fmaf(cf, acc.y, -f.y);
    o.z = fmaf(cf, acc.z, -f.z);
    o.w = fmaf(cf, acc.w, -f.w);
    T2[node * 16 + c] = o;
}

// ---------------------------------------------------------------------------
// fused GEMM: out = feat@W0 + (B*rnorm)@W1 + Tx2@W2 + bias
__global__ __launch_bounds__(256)
void gemm_kernel(const float* __restrict__ feat,
                 const float* __restrict__ W,
                 const float* __restrict__ bias,
                 float*       __restrict__ out) {
    __shared__ float As[64][65];
    __shared__ float Ws[64][64];

    const int m0 = blockIdx.x * 64;
    const int tx = threadIdx.x & 15;
    const int ty = threadIdx.x >> 4;

    float acc[4][4];
#pragma unroll
    for (int i = 0; i < 4; ++i)
#pragma unroll
        for (int j = 0; j < 4; ++j) acc[i][j] = 0.0f;

    for (int p = 0; p < 3; ++p) {
        const float* Ap = (p == 0) ? feat : (p == 1) ? g_B : g_T2;
#pragma unroll
        for (int i = 0; i < 16; ++i) {
            int idx = threadIdx.x + i * 256;
            Ws[idx >> 6][idx & 63] = W[p * 4096 + idx];
        }
#pragma unroll
        for (int i = 0; i < 16; ++i) {
            int idx  = threadIdx.x + i * 256;
            int m    = idx >> 6;
            int k    = idx & 63;
            int node = m0 + m;
            float v  = 0.0f;
            if (node < N_NODES) {
                v = Ap[node * 64 + k];
                if (p == 1) v *= g_rnorm[node];
            }
            As[k][m] = v;
        }
        __syncthreads();

#pragma unroll
        for (int k = 0; k < 64; ++k) {
            float a0 = As[k][ty * 4 + 0];
            float a1 = As[k][ty * 4 + 1];
            float a2 = As[k][ty * 4 + 2];
            float a3 = As[k][ty * 4 + 3];
            float4 w = *(const float4*)&Ws[k][tx * 4];
            acc[0][0] = fmaf(a0, w.x, acc[0][0]); acc[0][1] = fmaf(a0, w.y, acc[0][1]);
            acc[0][2] = fmaf(a0, w.z, acc[0][2]); acc[0][3] = fmaf(a0, w.w, acc[0][3]);
            acc[1][0] = fmaf(a1, w.x, acc[1][0]); acc[1][1] = fmaf(a1, w.y, acc[1][1]);
            acc[1][2] = fmaf(a1, w.z, acc[1][2]); acc[1][3] = fmaf(a1, w.w, acc[1][3]);
            acc[2][0] = fmaf(a2, w.x, acc[2][0]); acc[2][1] = fmaf(a2, w.y, acc[2][1]);
            acc[2][2] = fmaf(a2, w.z, acc[2][2]); acc[2][3] = fmaf(a2, w.w, acc[2][3]);
            acc[3][0] = fmaf(a3, w.x, acc[3][0]); acc[3][1] = fmaf(a3, w.y, acc[3][1]);
            acc[3][2] = fmaf(a3, w.z, acc[3][2]); acc[3][3] = fmaf(a3, w.w, acc[3][3]);
        }
        __syncthreads();
    }

    float4 b4 = *(const float4*)&bias[tx * 4];
#pragma unroll
    for (int i = 0; i < 4; ++i) {
        int node = m0 + ty * 4 + i;
        if (node < N_NODES) {
            float4 o;
            o.x = acc[i][0] + b4.x;
            o.y = acc[i][1] + b4.y;
            o.z = acc[i][2] + b4.z;
            o.w = acc[i][3] + b4.w;
            *(float4*)&out[node * 64 + tx * 4] = o;
        }
    }
}

// ---------------------------------------------------------------------------
extern "C" void kernel_launch(void* const* d_in, const int* in_sizes, int n_in,
                              void* d_out, int out_size) {
    const float* feat = (const float*)d_in[0];
    const float* W    = (const float*)d_in[1];
    const float* bias = (const float*)d_in[2];
    const int*   esrc = (const int*)d_in[3];
    const int*   edst = (const int*)d_in[4];
    float*       out  = (float*)d_out;

    void* p_degi; cudaGetSymbolAddress(&p_degi, g_degi);
    void* p_A;    cudaGetSymbolAddress(&p_A,    g_A);
    void* p_B;    cudaGetSymbolAddress(&p_B,    g_B);
    void* p_T2;   cudaGetSymbolAddress(&p_T2,   g_T2);

    cudaMemsetAsync(p_degi, 0, N_NODES * sizeof(int));

    deg_kernel <<<(N_EDGES + 255) / 256, 256>>>(edst);
    scan1_kernel<<<NB, 1024>>>();
    scan2_kernel<<<1, 128>>>();
    scan3_kernel<<<(N_NODES + 255) / 256, 256>>>();
    fill_kernel <<<(N_EDGES + 255) / 256, 256>>>(esrc, edst);

    const int ew = N_NODES * (DF / 4);
    prescale1_kernel<<<(ew + 255) / 256, 256>>>((const float4*)feat);
    gather1_kernel<<<(N_NODES + 15) / 16, 256>>>((const float4*)p_A, (float4*)p_B);
    gather2_kernel<<<(N_NODES + 15) / 16, 256>>>((const float4*)p_B,
                                                 (const float4*)feat, (float4*)p_T2);

    gemm_kernel<<<(N_NODES + 63) / 64, 256>>>(feat, W, bias, out);
}